// round 13
// baseline (speedup 1.0000x reference)
#include <cuda_runtime.h>
#include <math.h>

#define TT 2048
#define DD 256
#define NB 8
#define BTD (NB * TT * DD)
#define CAP 32
#define NPART 16

#define BM 128
#define BN 128
#define BK 16
#define PAD 132
#define PADS 132

typedef unsigned long long u64;

static __device__ float g_vb1[BTD];
static __device__ float g_vb2[BTD];
static __device__ float g_ab1[BTD];
static __device__ float g_ab2[BTD];
static __device__ float g_beta[(size_t)NB * TT * TT];
static __device__ float g_rowsum[NB * TT];
static __device__ float g_colsum[NB * TT];
static __device__ float g_rs_part[NPART][NB * TT];
static __device__ float g_cs_part[NPART][NB * TT];
static __device__ int   g_cnt_va[NB * TT];
static __device__ int   g_cnt_av[NB * TT];
static __device__ int   g_idx_va[NB * TT * CAP];
static __device__ int   g_idx_av[NB * TT * CAP];
static __device__ float g_val_va[NB * TT * CAP];
static __device__ float g_val_av[NB * TT * CAP];

// ---- packed f32x2 helpers --------------------------------------------------
__device__ __forceinline__ u64 pk2(float x, float y) {
    u64 r;
    asm("mov.b64 %0, {%1, %2};" : "=l"(r) : "f"(x), "f"(y));
    return r;
}
__device__ __forceinline__ void upk2(float& x, float& y, u64 v) {
    asm("mov.b64 {%0, %1}, %2;" : "=f"(x), "=f"(y) : "l"(v));
}
__device__ __forceinline__ void ffma2(u64& d, u64 a, u64 b) {
    asm("fma.rn.f32x2 %0, %1, %2, %0;" : "+l"(d) : "l"(a), "l"(b));
}

// ---------------------------------------------------------------------------
// beta[b, v, a] = relu( dot(vb2[b,v,:], ab1[b,a,:]) / 16 )  (NT GEMM, K=256)
// 128 threads, BM=BN=128, BK=16. Thread owns 8 row-pairs (rows s*16+ty*2)
// x 8 cols (tx*4+jj, 64+tx*4+jj). Staging stores for the next buffer are
// issued BETWEEN the two kk half-loops so STS retire under FFMA2 work.
// a-pairs loaded directly as u64; beta stores streaming (.cs).
// Epilogue fuses deterministic row/col partial sums.
// grid: (TT/128, TT/128, NB)
// ---------------------------------------------------------------------------
__global__ __launch_bounds__(128, 2) void beta_k() {
    __shared__ float As[2][BK][PADS];
    __shared__ float Bs[2][BK][PADS];
    const int tid = threadIdx.x;
    const int tx = tid & 15;        // 0..15
    const int ty = tid >> 4;        // 0..7
    const int bz = blockIdx.z;
    const int m0 = blockIdx.y * BM, n0 = blockIdx.x * BN;
    const float* Ag = g_vb2 + (size_t)bz * TT * DD;
    const float* Bg = g_ab1 + (size_t)bz * TT * DD;

    const int srow = tid >> 2;      // 0..31
    const int skq = tid & 3;        // k-offset = skq*4
    const float* Aptr = Ag + (size_t)(m0 + srow) * DD + skq * 4;
    const float* Bptr = Bg + (size_t)(n0 + srow) * DD + skq * 4;

    float4 pa[4], pb[4];
#pragma unroll
    for (int p = 0; p < 4; p++) {
        pa[p] = *(const float4*)(Aptr + (size_t)(p * 32) * DD);
        pb[p] = *(const float4*)(Bptr + (size_t)(p * 32) * DD);
    }
#pragma unroll
    for (int p = 0; p < 4; p++) {
        const float va[4] = {pa[p].x, pa[p].y, pa[p].z, pa[p].w};
        const float vb[4] = {pb[p].x, pb[p].y, pb[p].z, pb[p].w};
#pragma unroll
        for (int c = 0; c < 4; c++) {
            As[0][skq * 4 + c][srow + p * 32] = va[c];
            Bs[0][skq * 4 + c][srow + p * 32] = vb[c];
        }
    }
    __syncthreads();

    u64 acc2[8][8];
#pragma unroll
    for (int s = 0; s < 8; s++)
#pragma unroll
        for (int j = 0; j < 8; j++) acc2[s][j] = 0ull;

    int buf = 0;
#pragma unroll 1
    for (int t = 0; t < DD / BK; t++) {
        const int kn = (t + 1) * BK;
        const bool more = (t + 1 < DD / BK);
        if (more) {
#pragma unroll
            for (int p = 0; p < 4; p++) {
                pa[p] = *(const float4*)(Aptr + (size_t)(p * 32) * DD + kn);
                pb[p] = *(const float4*)(Bptr + (size_t)(p * 32) * DD + kn);
            }
        }
#pragma unroll
        for (int kk = 0; kk < BK / 2; kk++) {
            float4 b0 = *(const float4*)&Bs[buf][kk][tx * 4];
            float4 b1 = *(const float4*)&Bs[buf][kk][64 + tx * 4];
            u64 bd[8];
            bd[0] = pk2(b0.x, b0.x); bd[1] = pk2(b0.y, b0.y);
            bd[2] = pk2(b0.z, b0.z); bd[3] = pk2(b0.w, b0.w);
            bd[4] = pk2(b1.x, b1.x); bd[5] = pk2(b1.y, b1.y);
            bd[6] = pk2(b1.z, b1.z); bd[7] = pk2(b1.w, b1.w);
#pragma unroll
            for (int s = 0; s < 8; s++) {
                const u64 av = *(const u64*)&As[buf][kk][s * 16 + ty * 2];
#pragma unroll
                for (int j = 0; j < 8; j++) ffma2(acc2[s][j], av, bd[j]);
            }
        }
        if (more) {
            const int nb = buf ^ 1;
#pragma unroll
            for (int p = 0; p < 4; p++) {
                const float va[4] = {pa[p].x, pa[p].y, pa[p].z, pa[p].w};
                const float vb[4] = {pb[p].x, pb[p].y, pb[p].z, pb[p].w};
#pragma unroll
                for (int c = 0; c < 4; c++) {
                    As[nb][skq * 4 + c][srow + p * 32] = va[c];
                    Bs[nb][skq * 4 + c][srow + p * 32] = vb[c];
                }
            }
        }
#pragma unroll
        for (int kk = BK / 2; kk < BK; kk++) {
            float4 b0 = *(const float4*)&Bs[buf][kk][tx * 4];
            float4 b1 = *(const float4*)&Bs[buf][kk][64 + tx * 4];
            u64 bd[8];
            bd[0] = pk2(b0.x, b0.x); bd[1] = pk2(b0.y, b0.y);
            bd[2] = pk2(b0.z, b0.z); bd[3] = pk2(b0.w, b0.w);
            bd[4] = pk2(b1.x, b1.x); bd[5] = pk2(b1.y, b1.y);
            bd[6] = pk2(b1.z, b1.z); bd[7] = pk2(b1.w, b1.w);
#pragma unroll
            for (int s = 0; s < 8; s++) {
                const u64 av = *(const u64*)&As[buf][kk][s * 16 + ty * 2];
#pragma unroll
                for (int j = 0; j < 8; j++) ffma2(acc2[s][j], av, bd[j]);
            }
        }
        if (more) {
            __syncthreads();
            buf ^= 1;
        }
    }

    // ---- epilogue: scale+relu, write beta (.cs), fused row/col partials ----
    float* C = g_beta + (size_t)bz * TT * TT;
    float cpart[8] = {};
    float rpart[16];
#pragma unroll
    for (int s = 0; s < 8; s++) {
        float v0[8], v1[8];
        float rs0 = 0.f, rs1 = 0.f;
#pragma unroll
        for (int j = 0; j < 8; j++) {
            float lo, hi;
            upk2(lo, hi, acc2[s][j]);
            v0[j] = fmaxf(lo * 0.0625f, 0.f);
            v1[j] = fmaxf(hi * 0.0625f, 0.f);
            rs0 += v0[j];
            rs1 += v1[j];
            cpart[j] += v0[j] + v1[j];
        }
        rpart[s * 2 + 0] = rs0;
        rpart[s * 2 + 1] = rs1;
        const int r0 = m0 + s * 16 + ty * 2;
        float* cp0 = C + (size_t)r0 * TT + n0;
        float* cp1 = cp0 + TT;
        __stcs((float4*)(cp0 + tx * 4), make_float4(v0[0], v0[1], v0[2], v0[3]));
        __stcs((float4*)(cp0 + 64 + tx * 4), make_float4(v0[4], v0[5], v0[6], v0[7]));
        __stcs((float4*)(cp1 + tx * 4), make_float4(v1[0], v1[1], v1[2], v1[3]));
        __stcs((float4*)(cp1 + 64 + tx * 4), make_float4(v1[4], v1[5], v1[6], v1[7]));
    }

    // row partials: reduce over tx (16 lanes within each half-warp)
#pragma unroll
    for (int i = 0; i < 16; i++) {
        float r = rpart[i];
#pragma unroll
        for (int o = 8; o > 0; o >>= 1)
            r += __shfl_xor_sync(0xffffffffu, r, o);
        rpart[i] = r;
    }
    if (tx == 0) {
#pragma unroll
        for (int s = 0; s < 8; s++) {
            const int r0 = bz * TT + m0 + s * 16 + ty * 2;
            g_rs_part[blockIdx.x][r0 + 0] = rpart[s * 2 + 0];
            g_rs_part[blockIdx.x][r0 + 1] = rpart[s * 2 + 1];
        }
    }

    // col partials: reduce over ty via smem scratch (reuse As)
    __syncthreads();
    float* sc = &As[0][0][0];  // scratch [8][128]
#pragma unroll
    for (int j = 0; j < 4; j++) {
        sc[ty * 128 + tx * 4 + j] = cpart[j];
        sc[ty * 128 + 64 + tx * 4 + j] = cpart[4 + j];
    }
    __syncthreads();
    {
        float s = 0.f;
#pragma unroll
        for (int r = 0; r < 8; r++) s += sc[r * 128 + tid];
        g_cs_part[blockIdx.y][bz * TT + n0 + tid] = s;
    }
}

// ---------------------------------------------------------------------------
// Combine partial sums + zero sparse-list counters. Deterministic.
// ---------------------------------------------------------------------------
__global__ __launch_bounds__(256) void combine_sums_k() {
    const int i = blockIdx.x * 256 + threadIdx.x;
    float rs = 0.f, cs = 0.f;
#pragma unroll
    for (int p = 0; p < NPART; p++) {
        rs += g_rs_part[p][i];
        cs += g_cs_part[p][i];
    }
    g_rowsum[i] = rs;
    g_colsum[i] = cs;
    g_cnt_va[i] = 0;
    g_cnt_av[i] = 0;
}

// ---------------------------------------------------------------------------
// All four projection GEMMs in ONE launch: relu(x @ W).
// grid: (8, M/128); nt selects {v,a} x {W1,W2} x {n-tile}.
// 256 threads; thread owns 4 row-pairs (rows s*32+ty*2) x 8 cols.
// ---------------------------------------------------------------------------
__global__ __launch_bounds__(256, 2) void gemm_proj4(
        const float* __restrict__ Vf, const float* __restrict__ Af,
        const float* __restrict__ Wv1, const float* __restrict__ Wv2,
        const float* __restrict__ Wa1, const float* __restrict__ Wa2) {
    __shared__ float As[2][BK][PAD];
    __shared__ float Bs[2][BK][PAD];
    const int tid = threadIdx.x;
    const int m0 = blockIdx.y * BM;
    const int nt = blockIdx.x;           // 0..7
    const float* A = (nt < 4) ? Vf : Af;
    const float* W;
    float* C;
    {
        const int wsel = (nt >> 1) & 1;
        if (nt < 4) { W = wsel ? Wv2 : Wv1; C = wsel ? g_vb2 : g_vb1; }
        else        { W = wsel ? Wa2 : Wa1; C = wsel ? g_ab2 : g_ab1; }
    }
    const int n0 = (nt & 1) * BN;
    const int tx = tid & 15, ty = tid >> 4;   // ty 0..15
    const int alr = tid >> 2;
    const int alc = (tid & 3) * 4;
    const int blr = tid >> 5;
    const int blc = (tid & 31) * 4;
    const float* Aptr = A + (size_t)(m0 + alr) * DD + alc;
    const float* Wptr = W + (size_t)blr * DD + n0 + blc;

    float4 a0 = *(const float4*)(Aptr);
    float4 a1 = *(const float4*)(Aptr + (size_t)64 * DD);
    float4 b0 = *(const float4*)(Wptr);
    float4 b1 = *(const float4*)(Wptr + (size_t)8 * DD);
    As[0][alc + 0][alr] = a0.x; As[0][alc + 1][alr] = a0.y;
    As[0][alc + 2][alr] = a0.z; As[0][alc + 3][alr] = a0.w;
    As[0][alc + 0][alr + 64] = a1.x; As[0][alc + 1][alr + 64] = a1.y;
    As[0][alc + 2][alr + 64] = a1.z; As[0][alc + 3][alr + 64] = a1.w;
    *(float4*)&Bs[0][blr][blc] = b0;
    *(float4*)&Bs[0][blr + 8][blc] = b1;
    __syncthreads();

    u64 acc2[4][8];
#pragma unroll
    for (int s = 0; s < 4; s++)
#pragma unroll
        for (int j = 0; j < 8; j++) acc2[s][j] = 0ull;

    int buf = 0;
#pragma unroll 1
    for (int t = 0; t < DD / BK; t++) {
        const int kn = (t + 1) * BK;
        const bool more = (t + 1 < DD / BK);
        if (more) {
            a0 = *(const float4*)(Aptr + kn);
            a1 = *(const float4*)(Aptr + (size_t)64 * DD + kn);
            b0 = *(const float4*)(Wptr + (size_t)kn * DD);
            b1 = *(const float4*)(Wptr + (size_t)(kn + 8) * DD);
        }
#pragma unroll
        for (int kk = 0; kk < BK / 2; kk++) {
            float4 c0 = *(const float4*)&Bs[buf][kk][tx * 4];
            float4 c1 = *(const float4*)&Bs[buf][kk][64 + tx * 4];
            u64 bd[8];
            bd[0] = pk2(c0.x, c0.x); bd[1] = pk2(c0.y, c0.y);
            bd[2] = pk2(c0.z, c0.z); bd[3] = pk2(c0.w, c0.w);
            bd[4] = pk2(c1.x, c1.x); bd[5] = pk2(c1.y, c1.y);
            bd[6] = pk2(c1.z, c1.z); bd[7] = pk2(c1.w, c1.w);
#pragma unroll
            for (int s = 0; s < 4; s++) {
                const u64 av = *(const u64*)&As[buf][kk][s * 32 + ty * 2];
#pragma unroll
                for (int j = 0; j < 8; j++) ffma2(acc2[s][j], av, bd[j]);
            }
        }
        if (more) {
            const int nb = buf ^ 1;
            As[nb][alc + 0][alr] = a0.x; As[nb][alc + 1][alr] = a0.y;
            As[nb][alc + 2][alr] = a0.z; As[nb][alc + 3][alr] = a0.w;
            As[nb][alc + 0][alr + 64] = a1.x; As[nb][alc + 1][alr + 64] = a1.y;
            As[nb][alc + 2][alr + 64] = a1.z; As[nb][alc + 3][alr + 64] = a1.w;
            *(float4*)&Bs[nb][blr][blc] = b0;
            *(float4*)&Bs[nb][blr + 8][blc] = b1;
        }
#pragma unroll
        for (int kk = BK / 2; kk < BK; kk++) {
            float4 c0 = *(const float4*)&Bs[buf][kk][tx * 4];
            float4 c1 = *(const float4*)&Bs[buf][kk][64 + tx * 4];
            u64 bd[8];
            bd[0] = pk2(c0.x, c0.x); bd[1] = pk2(c0.y, c0.y);
            bd[2] = pk2(c0.z, c0.z); bd[3] = pk2(c0.w, c0.w);
            bd[4] = pk2(c1.x, c1.x); bd[5] = pk2(c1.y, c1.y);
            bd[6] = pk2(c1.z, c1.z); bd[7] = pk2(c1.w, c1.w);
#pragma unroll
            for (int s = 0; s < 4; s++) {
                const u64 av = *(const u64*)&As[buf][kk][s * 32 + ty * 2];
#pragma unroll
                for (int j = 0; j < 8; j++) ffma2(acc2[s][j], av, bd[j]);
            }
        }
        if (more) {
            __syncthreads();
            buf ^= 1;
        }
    }
#pragma unroll
    for (int s = 0; s < 4; s++) {
        float v0[8], v1[8];
#pragma unroll
        for (int j = 0; j < 8; j++) {
            float lo, hi;
            upk2(lo, hi, acc2[s][j]);
            v0[j] = fmaxf(lo, 0.f);
            v1[j] = fmaxf(hi, 0.f);
        }
        const int r0 = m0 + s * 32 + ty * 2;
        float* cp0 = C + (size_t)r0 * DD + n0;
        float* cp1 = cp0 + DD;
        *(float4*)(cp0 + tx * 4) = make_float4(v0[0], v0[1], v0[2], v0[3]);
        *(float4*)(cp0 + 64 + tx * 4) = make_float4(v0[4], v0[5], v0[6], v0[7]);
        *(float4*)(cp1 + tx * 4) = make_float4(v1[0], v1[1], v1[2], v1[3]);
        *(float4*)(cp1 + 64 + tx * 4) = make_float4(v1[4], v1[5], v1[6], v1[7]);
    }
}

// ---------------------------------------------------------------------------
// Select: TWO rows per block (4 independent LDG.128/thread for MLP).
// Survivors (<=10 at thr=0.099; CAP=32 safe) go into per-row sparse lists.
// grid: NB*TT/2 blocks.
// ---------------------------------------------------------------------------
__global__ __launch_bounds__(256) void select_k(const float* __restrict__ thrp) {
    const int row0 = blockIdx.x * 2;     // b*TT + v0, v0 even
    const int b = row0 >> 11;
    const int v0 = row0 & (TT - 1);
    const float* rp0 = g_beta + (size_t)row0 * TT;
    const float* rp1 = rp0 + TT;
    const int a0 = threadIdx.x * 8;

    const float4 p0 = __ldcs((const float4*)(rp0 + a0));
    const float4 p1 = __ldcs((const float4*)(rp0 + a0 + 4));
    const float4 q0 = __ldcs((const float4*)(rp1 + a0));
    const float4 q1 = __ldcs((const float4*)(rp1 + a0 + 4));
    const float4 c0 = *(const float4*)(g_colsum + b * TT + a0);
    const float4 c1 = *(const float4*)(g_colsum + b * TT + a0 + 4);
    const float thr = __ldg(thrp);
    const float rsA = g_rowsum[row0] + 1e-8f;
    const float rsB = g_rowsum[row0 + 1] + 1e-8f;
    const float thrA = thr * rsA;
    const float thrB = thr * rsB;

    const float bA[8] = {p0.x, p0.y, p0.z, p0.w, p1.x, p1.y, p1.z, p1.w};
    const float bB[8] = {q0.x, q0.y, q0.z, q0.w, q1.x, q1.y, q1.z, q1.w};
    const float cc[8] = {c0.x, c0.y, c0.z, c0.w, c1.x, c1.y, c1.z, c1.w};
#pragma unroll
    for (int i = 0; i < 8; i++) {
        const int a = a0 + i;
        const float cs = cc[i] + 1e-8f;
        const float thrC = thr * cs;
        if (bA[i] > thrA) {
            const int p = atomicAdd(&g_cnt_va[row0], 1);
            if (p < CAP) {
                g_idx_va[row0 * CAP + p] = a;
                g_val_va[row0 * CAP + p] = bA[i] / rsA;
            }
        }
        if (bB[i] > thrB) {
            const int p = atomicAdd(&g_cnt_va[row0 + 1], 1);
            if (p < CAP) {
                g_idx_va[(row0 + 1) * CAP + p] = a;
                g_val_va[(row0 + 1) * CAP + p] = bB[i] / rsB;
            }
        }
        if (bA[i] > thrC) {
            const int p = atomicAdd(&g_cnt_av[b * TT + a], 1);
            if (p < CAP) {
                g_idx_av[(b * TT + a) * CAP + p] = v0;
                g_val_av[(b * TT + a) * CAP + p] = bA[i] / cs;
            }
        }
        if (bB[i] > thrC) {
            const int p = atomicAdd(&g_cnt_av[b * TT + a], 1);
            if (p < CAP) {
                g_idx_av[(b * TT + a) * CAP + p] = v0 + 1;
                g_val_av[(b * TT + a) * CAP + p] = bB[i] / cs;
            }
        }
    }
}

// ---------------------------------------------------------------------------
// Final: sparse gathers + residual + dual LayerNorm + average.
// ---------------------------------------------------------------------------
__global__ __launch_bounds__(256) void ln_combine_sparse(
        const float* __restrict__ v_fea, const float* __restrict__ a_fea,
        const float* __restrict__ gam, const float* __restrict__ bet,
        float* __restrict__ out) {
    const int row = blockIdx.x;
    const int b = row >> 11;
    const int h = threadIdx.x;
    const size_t idx = (size_t)row * DD + h;
    const size_t base = (size_t)b * TT * DD;

    __shared__ int s_n1, s_n2;
    __shared__ int s_i1[CAP], s_i2[CAP];
    __shared__ float s_w1[CAP], s_w2[CAP];
    if (h == 0) {
        int n1 = g_cnt_va[row]; s_n1 = n1 < CAP ? n1 : CAP;
        int n2 = g_cnt_av[row]; s_n2 = n2 < CAP ? n2 : CAP;
    }
    __syncthreads();
    if (h < s_n1) { s_i1[h] = g_idx_va[row * CAP + h]; s_w1[h] = g_val_va[row * CAP + h]; }
    if (h < s_n2) { s_i2[h] = g_idx_av[row * CAP + h]; s_w2[h] = g_val_av[row * CAP + h]; }
    __syncthreads();

    float apos = 0.f, vpos = 0.f;
    const int n1 = s_n1, n2 = s_n2;
    for (int i = 0; i < n1; i++)
        apos += s_w1[i] * g_ab2[base + (size_t)s_i1[i] * DD + h];
    for (int i = 0; i < n2; i++)
        vpos += s_w2[i] * g_vb1[base + (size_t)s_i2[i] * DD + h];

    const float x1 = v_fea[idx] + apos;
    const float x2 = a_fea[idx] + vpos;
    float4 v = make_float4(x1, x1 * x1, x2, x2 * x2);
    __shared__ float4 smv[8];
    const int lane = h & 31, w = h >> 5;
#pragma unroll
    for (int o = 16; o > 0; o >>= 1) {
        v.x += __shfl_down_sync(0xffffffffu, v.x, o);
        v.y += __shfl_down_sync(0xffffffffu, v.y, o);
        v.z += __shfl_down_sync(0xffffffffu, v.z, o);
        v.w += __shfl_down_sync(0xffffffffu, v.w, o);
    }
    if (lane == 0) smv[w] = v;
    __syncthreads();
    if (w == 0) {
        v = (lane < 8) ? smv[lane] : make_float4(0.f, 0.f, 0.f, 0.f);
#pragma unroll
        for (int o = 4; o > 0; o >>= 1) {
            v.x += __shfl_down_sync(0xffffffffu, v.x, o);
            v.y += __shfl_down_sync(0xffffffffu, v.y, o);
            v.z += __shfl_down_sync(0xffffffffu, v.z, o);
            v.w += __shfl_down_sync(0xffffffffu, v.w, o);
        }
        if (lane == 0) smv[0] = v;
    }
    __syncthreads();
    v = smv[0];
    const float inv = 1.f / (float)DD;
    const float mu1 = v.x * inv, var1 = v.y * inv - mu1 * mu1;
    const float mu2 = v.z * inv, var2 = v.w * inv - mu2 * mu2;
    const float g = gam[h], be = bet[h];
    const float y1 = (x1 - mu1) * rsqrtf(var1 + 1e-6f) * g + be;
    const float y2 = (x2 - mu2) * rsqrtf(var2 + 1e-6f) * g + be;
    out[idx] = 0.5f * (y1 + y2);
}

// ---------------------------------------------------------------------------
extern "C" void kernel_launch(void* const* d_in, const int* in_sizes, int n_in,
                              void* d_out, int out_size) {
    const float* a_fea = (const float*)d_in[0];
    const float* v_fea = (const float*)d_in[1];
    const float* Wv1 = (const float*)d_in[2];
    const float* Wv2 = (const float*)d_in[3];
    const float* Wa1 = (const float*)d_in[4];
    const float* Wa2 = (const float*)d_in[5];
    const float* ln_g = (const float*)d_in[6];
    const float* ln_b = (const float*)d_in[7];
    const float* thr = (const float*)d_in[8];
    float* out = (float*)d_out;

    gemm_proj4<<<dim3(8, (NB * TT) / BM), 256>>>(v_fea, a_fea,
                                                 Wv1, Wv2, Wa1, Wa2);

    beta_k<<<dim3(TT / BN, TT / BM, NB), 128>>>();
    combine_sums_k<<<(NB * TT) / 256, 256>>>();

    select_k<<<(NB * TT) / 2, 256>>>(thr);

    ln_combine_sparse<<<NB * TT, 256>>>(v_fea, a_fea, ln_g, ln_b, out);
}

// round 14
// speedup vs baseline: 1.0259x; 1.0259x over previous
#include <cuda_runtime.h>
#include <math.h>

#define TT 2048
#define DD 256
#define NB 8
#define BTD (NB * TT * DD)
#define CAP 32
#define NPART 16

#define BM 128
#define BN 128
#define BK 16
#define PAD 132
#define PADS 132

typedef unsigned long long u64;

static __device__ float g_vb1[BTD];
static __device__ float g_vb2[BTD];
static __device__ float g_ab1[BTD];
static __device__ float g_ab2[BTD];
static __device__ float g_beta[(size_t)NB * TT * TT];
static __device__ float g_rowsum[NB * TT];
static __device__ float g_colsum[NB * TT];
static __device__ float g_rs_part[NPART][NB * TT];
static __device__ float g_cs_part[NPART][NB * TT];
static __device__ int   g_cnt_va[NB * TT];
static __device__ int   g_cnt_av[NB * TT];
static __device__ int   g_idx_va[NB * TT * CAP];
static __device__ int   g_idx_av[NB * TT * CAP];
static __device__ float g_val_va[NB * TT * CAP];
static __device__ float g_val_av[NB * TT * CAP];

// ---- packed f32x2 helpers --------------------------------------------------
__device__ __forceinline__ u64 pk2(float x, float y) {
    u64 r;
    asm("mov.b64 %0, {%1, %2};" : "=l"(r) : "f"(x), "f"(y));
    return r;
}
__device__ __forceinline__ void upk2(float& x, float& y, u64 v) {
    asm("mov.b64 {%0, %1}, %2;" : "=f"(x), "=f"(y) : "l"(v));
}
__device__ __forceinline__ void ffma2(u64& d, u64 a, u64 b) {
    asm("fma.rn.f32x2 %0, %1, %2, %0;" : "+l"(d) : "l"(a), "l"(b));
}

// ---------------------------------------------------------------------------
// beta[b, v, a] = relu( dot(vb2[b,v,:], ab1[b,a,:]) / 16 )  (NT GEMM, K=256)
// 128 threads, BM=BN=128, BK=16. Thread owns 8 row-pairs (rows s*16+ty*2)
// x 8 cols (tx*4+jj, 64+tx*4+jj). Staging stores for the next buffer are
// issued BETWEEN the two kk half-loops so STS retire under FFMA2 work.
// beta stores use streaming hint (.cs) — written once, read once.
// Epilogue fuses deterministic row/col partial sums.
// grid: (TT/128, TT/128, NB)
// ---------------------------------------------------------------------------
__global__ __launch_bounds__(128, 2) void beta_k() {
    __shared__ float As[2][BK][PADS];
    __shared__ float Bs[2][BK][PADS];
    const int tid = threadIdx.x;
    const int tx = tid & 15;        // 0..15
    const int ty = tid >> 4;        // 0..7
    const int bz = blockIdx.z;
    const int m0 = blockIdx.y * BM, n0 = blockIdx.x * BN;
    const float* Ag = g_vb2 + (size_t)bz * TT * DD;
    const float* Bg = g_ab1 + (size_t)bz * TT * DD;

    const int srow = tid >> 2;      // 0..31
    const int skq = tid & 3;        // k-offset = skq*4
    const float* Aptr = Ag + (size_t)(m0 + srow) * DD + skq * 4;
    const float* Bptr = Bg + (size_t)(n0 + srow) * DD + skq * 4;

    float4 pa[4], pb[4];
#pragma unroll
    for (int p = 0; p < 4; p++) {
        pa[p] = *(const float4*)(Aptr + (size_t)(p * 32) * DD);
        pb[p] = *(const float4*)(Bptr + (size_t)(p * 32) * DD);
    }
#pragma unroll
    for (int p = 0; p < 4; p++) {
        const float va[4] = {pa[p].x, pa[p].y, pa[p].z, pa[p].w};
        const float vb[4] = {pb[p].x, pb[p].y, pb[p].z, pb[p].w};
#pragma unroll
        for (int c = 0; c < 4; c++) {
            As[0][skq * 4 + c][srow + p * 32] = va[c];
            Bs[0][skq * 4 + c][srow + p * 32] = vb[c];
        }
    }
    __syncthreads();

    u64 acc2[8][8];
#pragma unroll
    for (int s = 0; s < 8; s++)
#pragma unroll
        for (int j = 0; j < 8; j++) acc2[s][j] = 0ull;

    int buf = 0;
#pragma unroll 1
    for (int t = 0; t < DD / BK; t++) {
        const int kn = (t + 1) * BK;
        const bool more = (t + 1 < DD / BK);
        if (more) {
#pragma unroll
            for (int p = 0; p < 4; p++) {
                pa[p] = *(const float4*)(Aptr + (size_t)(p * 32) * DD + kn);
                pb[p] = *(const float4*)(Bptr + (size_t)(p * 32) * DD + kn);
            }
        }
#pragma unroll
        for (int kk = 0; kk < BK / 2; kk++) {
            float4 b0 = *(const float4*)&Bs[buf][kk][tx * 4];
            float4 b1 = *(const float4*)&Bs[buf][kk][64 + tx * 4];
            u64 bd[8];
            bd[0] = pk2(b0.x, b0.x); bd[1] = pk2(b0.y, b0.y);
            bd[2] = pk2(b0.z, b0.z); bd[3] = pk2(b0.w, b0.w);
            bd[4] = pk2(b1.x, b1.x); bd[5] = pk2(b1.y, b1.y);
            bd[6] = pk2(b1.z, b1.z); bd[7] = pk2(b1.w, b1.w);
#pragma unroll
            for (int s = 0; s < 8; s++) {
                const float2 ap =
                    *(const float2*)&As[buf][kk][s * 16 + ty * 2];
                const u64 av = pk2(ap.x, ap.y);
#pragma unroll
                for (int j = 0; j < 8; j++) ffma2(acc2[s][j], av, bd[j]);
            }
        }
        if (more) {
            const int nb = buf ^ 1;
#pragma unroll
            for (int p = 0; p < 4; p++) {
                const float va[4] = {pa[p].x, pa[p].y, pa[p].z, pa[p].w};
                const float vb[4] = {pb[p].x, pb[p].y, pb[p].z, pb[p].w};
#pragma unroll
                for (int c = 0; c < 4; c++) {
                    As[nb][skq * 4 + c][srow + p * 32] = va[c];
                    Bs[nb][skq * 4 + c][srow + p * 32] = vb[c];
                }
            }
        }
#pragma unroll
        for (int kk = BK / 2; kk < BK; kk++) {
            float4 b0 = *(const float4*)&Bs[buf][kk][tx * 4];
            float4 b1 = *(const float4*)&Bs[buf][kk][64 + tx * 4];
            u64 bd[8];
            bd[0] = pk2(b0.x, b0.x); bd[1] = pk2(b0.y, b0.y);
            bd[2] = pk2(b0.z, b0.z); bd[3] = pk2(b0.w, b0.w);
            bd[4] = pk2(b1.x, b1.x); bd[5] = pk2(b1.y, b1.y);
            bd[6] = pk2(b1.z, b1.z); bd[7] = pk2(b1.w, b1.w);
#pragma unroll
            for (int s = 0; s < 8; s++) {
                const float2 ap =
                    *(const float2*)&As[buf][kk][s * 16 + ty * 2];
                const u64 av = pk2(ap.x, ap.y);
#pragma unroll
                for (int j = 0; j < 8; j++) ffma2(acc2[s][j], av, bd[j]);
            }
        }
        if (more) {
            __syncthreads();
            buf ^= 1;
        }
    }

    // ---- epilogue: scale+relu, write beta (.cs), fused row/col partials ----
    float* C = g_beta + (size_t)bz * TT * TT;
    float cpart[8] = {};
    float rpart[16];
#pragma unroll
    for (int s = 0; s < 8; s++) {
        float v0[8], v1[8];
        float rs0 = 0.f, rs1 = 0.f;
#pragma unroll
        for (int j = 0; j < 8; j++) {
            float lo, hi;
            upk2(lo, hi, acc2[s][j]);
            v0[j] = fmaxf(lo * 0.0625f, 0.f);
            v1[j] = fmaxf(hi * 0.0625f, 0.f);
            rs0 += v0[j];
            rs1 += v1[j];
            cpart[j] += v0[j] + v1[j];
        }
        rpart[s * 2 + 0] = rs0;
        rpart[s * 2 + 1] = rs1;
        const int r0 = m0 + s * 16 + ty * 2;
        float* cp0 = C + (size_t)r0 * TT + n0;
        float* cp1 = cp0 + TT;
        __stcs((float4*)(cp0 + tx * 4), make_float4(v0[0], v0[1], v0[2], v0[3]));
        __stcs((float4*)(cp0 + 64 + tx * 4), make_float4(v0[4], v0[5], v0[6], v0[7]));
        __stcs((float4*)(cp1 + tx * 4), make_float4(v1[0], v1[1], v1[2], v1[3]));
        __stcs((float4*)(cp1 + 64 + tx * 4), make_float4(v1[4], v1[5], v1[6], v1[7]));
    }

    // row partials: reduce over tx (16 lanes within each half-warp)
#pragma unroll
    for (int i = 0; i < 16; i++) {
        float r = rpart[i];
#pragma unroll
        for (int o = 8; o > 0; o >>= 1)
            r += __shfl_xor_sync(0xffffffffu, r, o);
        rpart[i] = r;
    }
    if (tx == 0) {
#pragma unroll
        for (int s = 0; s < 8; s++) {
            const int r0 = bz * TT + m0 + s * 16 + ty * 2;
            g_rs_part[blockIdx.x][r0 + 0] = rpart[s * 2 + 0];
            g_rs_part[blockIdx.x][r0 + 1] = rpart[s * 2 + 1];
        }
    }

    // col partials: reduce over ty via smem scratch (reuse As)
    __syncthreads();
    float* sc = &As[0][0][0];  // scratch [8][128]
#pragma unroll
    for (int j = 0; j < 4; j++) {
        sc[ty * 128 + tx * 4 + j] = cpart[j];
        sc[ty * 128 + 64 + tx * 4 + j] = cpart[4 + j];
    }
    __syncthreads();
    {
        float s = 0.f;
#pragma unroll
        for (int r = 0; r < 8; r++) s += sc[r * 128 + tid];
        g_cs_part[blockIdx.y][bz * TT + n0 + tid] = s;
    }
}

// ---------------------------------------------------------------------------
// Combine partial sums + zero sparse-list counters. Deterministic.
// ---------------------------------------------------------------------------
__global__ __launch_bounds__(256) void combine_sums_k() {
    const int i = blockIdx.x * 256 + threadIdx.x;
    float rs = 0.f, cs = 0.f;
#pragma unroll
    for (int p = 0; p < NPART; p++) {
        rs += g_rs_part[p][i];
        cs += g_cs_part[p][i];
    }
    g_rowsum[i] = rs;
    g_colsum[i] = cs;
    g_cnt_va[i] = 0;
    g_cnt_av[i] = 0;
}

// ---------------------------------------------------------------------------
// All four projection GEMMs in ONE launch: relu(x @ W).
// grid: (8, M/128); nt selects {v,a} x {W1,W2} x {n-tile}.
// 256 threads; thread owns 4 row-pairs (rows s*32+ty*2) x 8 cols.
// ---------------------------------------------------------------------------
__global__ __launch_bounds__(256, 2) void gemm_proj4(
        const float* __restrict__ Vf, const float* __restrict__ Af,
        const float* __restrict__ Wv1, const float* __restrict__ Wv2,
        const float* __restrict__ Wa1, const float* __restrict__ Wa2) {
    __shared__ float As[2][BK][PAD];
    __shared__ float Bs[2][BK][PAD];
    const int tid = threadIdx.x;
    const int m0 = blockIdx.y * BM;
    const int nt = blockIdx.x;           // 0..7
    const float* A = (nt < 4) ? Vf : Af;
    const float* W;
    float* C;
    {
        const int wsel = (nt >> 1) & 1;
        if (nt < 4) { W = wsel ? Wv2 : Wv1; C = wsel ? g_vb2 : g_vb1; }
        else        { W = wsel ? Wa2 : Wa1; C = wsel ? g_ab2 : g_ab1; }
    }
    const int n0 = (nt & 1) * BN;
    const int tx = tid & 15, ty = tid >> 4;   // ty 0..15
    const int alr = tid >> 2;
    const int alc = (tid & 3) * 4;
    const int blr = tid >> 5;
    const int blc = (tid & 31) * 4;
    const float* Aptr = A + (size_t)(m0 + alr) * DD + alc;
    const float* Wptr = W + (size_t)blr * DD + n0 + blc;

    float4 a0 = *(const float4*)(Aptr);
    float4 a1 = *(const float4*)(Aptr + (size_t)64 * DD);
    float4 b0 = *(const float4*)(Wptr);
    float4 b1 = *(const float4*)(Wptr + (size_t)8 * DD);
    As[0][alc + 0][alr] = a0.x; As[0][alc + 1][alr] = a0.y;
    As[0][alc + 2][alr] = a0.z; As[0][alc + 3][alr] = a0.w;
    As[0][alc + 0][alr + 64] = a1.x; As[0][alc + 1][alr + 64] = a1.y;
    As[0][alc + 2][alr + 64] = a1.z; As[0][alc + 3][alr + 64] = a1.w;
    *(float4*)&Bs[0][blr][blc] = b0;
    *(float4*)&Bs[0][blr + 8][blc] = b1;
    __syncthreads();

    u64 acc2[4][8];
#pragma unroll
    for (int s = 0; s < 4; s++)
#pragma unroll
        for (int j = 0; j < 8; j++) acc2[s][j] = 0ull;

    int buf = 0;
#pragma unroll 1
    for (int t = 0; t < DD / BK; t++) {
        const int kn = (t + 1) * BK;
        const bool more = (t + 1 < DD / BK);
        if (more) {
            a0 = *(const float4*)(Aptr + kn);
            a1 = *(const float4*)(Aptr + (size_t)64 * DD + kn);
            b0 = *(const float4*)(Wptr + (size_t)kn * DD);
            b1 = *(const float4*)(Wptr + (size_t)(kn + 8) * DD);
        }
#pragma unroll
        for (int kk = 0; kk < BK / 2; kk++) {
            float4 c0 = *(const float4*)&Bs[buf][kk][tx * 4];
            float4 c1 = *(const float4*)&Bs[buf][kk][64 + tx * 4];
            u64 bd[8];
            bd[0] = pk2(c0.x, c0.x); bd[1] = pk2(c0.y, c0.y);
            bd[2] = pk2(c0.z, c0.z); bd[3] = pk2(c0.w, c0.w);
            bd[4] = pk2(c1.x, c1.x); bd[5] = pk2(c1.y, c1.y);
            bd[6] = pk2(c1.z, c1.z); bd[7] = pk2(c1.w, c1.w);
#pragma unroll
            for (int s = 0; s < 4; s++) {
                const float2 ap =
                    *(const float2*)&As[buf][kk][s * 32 + ty * 2];
                const u64 av = pk2(ap.x, ap.y);
#pragma unroll
                for (int j = 0; j < 8; j++) ffma2(acc2[s][j], av, bd[j]);
            }
        }
        if (more) {
            const int nb = buf ^ 1;
            As[nb][alc + 0][alr] = a0.x; As[nb][alc + 1][alr] = a0.y;
            As[nb][alc + 2][alr] = a0.z; As[nb][alc + 3][alr] = a0.w;
            As[nb][alc + 0][alr + 64] = a1.x; As[nb][alc + 1][alr + 64] = a1.y;
            As[nb][alc + 2][alr + 64] = a1.z; As[nb][alc + 3][alr + 64] = a1.w;
            *(float4*)&Bs[nb][blr][blc] = b0;
            *(float4*)&Bs[nb][blr + 8][blc] = b1;
        }
#pragma unroll
        for (int kk = BK / 2; kk < BK; kk++) {
            float4 c0 = *(const float4*)&Bs[buf][kk][tx * 4];
            float4 c1 = *(const float4*)&Bs[buf][kk][64 + tx * 4];
            u64 bd[8];
            bd[0] = pk2(c0.x, c0.x); bd[1] = pk2(c0.y, c0.y);
            bd[2] = pk2(c0.z, c0.z); bd[3] = pk2(c0.w, c0.w);
            bd[4] = pk2(c1.x, c1.x); bd[5] = pk2(c1.y, c1.y);
            bd[6] = pk2(c1.z, c1.z); bd[7] = pk2(c1.w, c1.w);
#pragma unroll
            for (int s = 0; s < 4; s++) {
                const float2 ap =
                    *(const float2*)&As[buf][kk][s * 32 + ty * 2];
                const u64 av = pk2(ap.x, ap.y);
#pragma unroll
                for (int j = 0; j < 8; j++) ffma2(acc2[s][j], av, bd[j]);
            }
        }
        if (more) {
            __syncthreads();
            buf ^= 1;
        }
    }
#pragma unroll
    for (int s = 0; s < 4; s++) {
        float v0[8], v1[8];
#pragma unroll
        for (int j = 0; j < 8; j++) {
            float lo, hi;
            upk2(lo, hi, acc2[s][j]);
            v0[j] = fmaxf(lo, 0.f);
            v1[j] = fmaxf(hi, 0.f);
        }
        const int r0 = m0 + s * 32 + ty * 2;
        float* cp0 = C + (size_t)r0 * DD + n0;
        float* cp1 = cp0 + DD;
        *(float4*)(cp0 + tx * 4) = make_float4(v0[0], v0[1], v0[2], v0[3]);
        *(float4*)(cp0 + 64 + tx * 4) = make_float4(v0[4], v0[5], v0[6], v0[7]);
        *(float4*)(cp1 + tx * 4) = make_float4(v1[0], v1[1], v1[2], v1[3]);
        *(float4*)(cp1 + 64 + tx * 4) = make_float4(v1[4], v1[5], v1[6], v1[7]);
    }
}

// ---------------------------------------------------------------------------
// Select: TWO rows per block (4 independent LDG.128/thread for MLP).
// Survivors (<=10 at thr=0.099; CAP=32 safe) go into per-row sparse lists.
// grid: NB*TT/2 blocks.
// ---------------------------------------------------------------------------
__global__ __launch_bounds__(256) void select_k(const float* __restrict__ thrp) {
    const int row0 = blockIdx.x * 2;     // b*TT + v0, v0 even
    const int b = row0 >> 11;
    const int v0 = row0 & (TT - 1);
    const float* rp0 = g_beta + (size_t)row0 * TT;
    const float* rp1 = rp0 + TT;
    const int a0 = threadIdx.x * 8;

    const float4 p0 = __ldcs((const float4*)(rp0 + a0));
    const float4 p1 = __ldcs((const float4*)(rp0 + a0 + 4));
    const float4 q0 = __ldcs((const float4*)(rp1 + a0));
    const float4 q1 = __ldcs((const float4*)(rp1 + a0 + 4));
    const float4 c0 = *(const float4*)(g_colsum + b * TT + a0);
    const float4 c1 = *(const float4*)(g_colsum + b * TT + a0 + 4);
    const float thr = __ldg(thrp);
    const float rsA = g_rowsum[row0] + 1e-8f;
    const float rsB = g_rowsum[row0 + 1] + 1e-8f;
    const float thrA = thr * rsA;
    const float thrB = thr * rsB;

    const float bA[8] = {p0.x, p0.y, p0.z, p0.w, p1.x, p1.y, p1.z, p1.w};
    const float bB[8] = {q0.x, q0.y, q0.z, q0.w, q1.x, q1.y, q1.z, q1.w};
    const float cc[8] = {c0.x, c0.y, c0.z, c0.w, c1.x, c1.y, c1.z, c1.w};
#pragma unroll
    for (int i = 0; i < 8; i++) {
        const int a = a0 + i;
        const float cs = cc[i] + 1e-8f;
        const float thrC = thr * cs;
        if (bA[i] > thrA) {
            const int p = atomicAdd(&g_cnt_va[row0], 1);
            if (p < CAP) {
                g_idx_va[row0 * CAP + p] = a;
                g_val_va[row0 * CAP + p] = bA[i] / rsA;
            }
        }
        if (bB[i] > thrB) {
            const int p = atomicAdd(&g_cnt_va[row0 + 1], 1);
            if (p < CAP) {
                g_idx_va[(row0 + 1) * CAP + p] = a;
                g_val_va[(row0 + 1) * CAP + p] = bB[i] / rsB;
            }
        }
        if (bA[i] > thrC) {
            const int p = atomicAdd(&g_cnt_av[b * TT + a], 1);
            if (p < CAP) {
                g_idx_av[(b * TT + a) * CAP + p] = v0;
                g_val_av[(b * TT + a) * CAP + p] = bA[i] / cs;
            }
        }
        if (bB[i] > thrC) {
            const int p = atomicAdd(&g_cnt_av[b * TT + a], 1);
            if (p < CAP) {
                g_idx_av[(b * TT + a) * CAP + p] = v0 + 1;
                g_val_av[(b * TT + a) * CAP + p] = bB[i] / cs;
            }
        }
    }
}

// ---------------------------------------------------------------------------
// Final: sparse gathers + residual + dual LayerNorm + average.
// ---------------------------------------------------------------------------
__global__ __launch_bounds__(256) void ln_combine_sparse(
        const float* __restrict__ v_fea, const float* __restrict__ a_fea,
        const float* __restrict__ gam, const float* __restrict__ bet,
        float* __restrict__ out) {
    const int row = blockIdx.x;
    const int b = row >> 11;
    const int h = threadIdx.x;
    const size_t idx = (size_t)row * DD + h;
    const size_t base = (size_t)b * TT * DD;

    __shared__ int s_n1, s_n2;
    __shared__ int s_i1[CAP], s_i2[CAP];
    __shared__ float s_w1[CAP], s_w2[CAP];
    if (h == 0) {
        int n1 = g_cnt_va[row]; s_n1 = n1 < CAP ? n1 : CAP;
        int n2 = g_cnt_av[row]; s_n2 = n2 < CAP ? n2 : CAP;
    }
    __syncthreads();
    if (h < s_n1) { s_i1[h] = g_idx_va[row * CAP + h]; s_w1[h] = g_val_va[row * CAP + h]; }
    if (h < s_n2) { s_i2[h] = g_idx_av[row * CAP + h]; s_w2[h] = g_val_av[row * CAP + h]; }
    __syncthreads();

    float apos = 0.f, vpos = 0.f;
    const int n1 = s_n1, n2 = s_n2;
    for (int i = 0; i < n1; i++)
        apos += s_w1[i] * g_ab2[base + (size_t)s_i1[i] * DD + h];
    for (int i = 0; i < n2; i++)
        vpos += s_w2[i] * g_vb1[base + (size_t)s_i2[i] * DD + h];

    const float x1 = v_fea[idx] + apos;
    const float x2 = a_fea[idx] + vpos;
    float4 v = make_float4(x1, x1 * x1, x2, x2 * x2);
    __shared__ float4 smv[8];
    const int lane = h & 31, w = h >> 5;
#pragma unroll
    for (int o = 16; o > 0; o >>= 1) {
        v.x += __shfl_down_sync(0xffffffffu, v.x, o);
        v.y += __shfl_down_sync(0xffffffffu, v.y, o);
        v.z += __shfl_down_sync(0xffffffffu, v.z, o);
        v.w += __shfl_down_sync(0xffffffffu, v.w, o);
    }
    if (lane == 0) smv[w] = v;
    __syncthreads();
    if (w == 0) {
        v = (lane < 8) ? smv[lane] : make_float4(0.f, 0.f, 0.f, 0.f);
#pragma unroll
        for (int o = 4; o > 0; o >>= 1) {
            v.x += __shfl_down_sync(0xffffffffu, v.x, o);
            v.y += __shfl_down_sync(0xffffffffu, v.y, o);
            v.z += __shfl_down_sync(0xffffffffu, v.z, o);
            v.w += __shfl_down_sync(0xffffffffu, v.w, o);
        }
        if (lane == 0) smv[0] = v;
    }
    __syncthreads();
    v = smv[0];
    const float inv = 1.f / (float)DD;
    const float mu1 = v.x * inv, var1 = v.y * inv - mu1 * mu1;
    const float mu2 = v.z * inv, var2 = v.w * inv - mu2 * mu2;
    const float g = gam[h], be = bet[h];
    const float y1 = (x1 - mu1) * rsqrtf(var1 + 1e-6f) * g + be;
    const float y2 = (x2 - mu2) * rsqrtf(var2 + 1e-6f) * g + be;
    out[idx] = 0.5f * (y1 + y2);
}

// ---------------------------------------------------------------------------
extern "C" void kernel_launch(void* const* d_in, const int* in_sizes, int n_in,
                              void* d_out, int out_size) {
    const float* a_fea = (const float*)d_in[0];
    const float* v_fea = (const float*)d_in[1];
    const float* Wv1 = (const float*)d_in[2];
    const float* Wv2 = (const float*)d_in[3];
    const float* Wa1 = (const float*)d_in[4];
    const float* Wa2 = (const float*)d_in[5];
    const float* ln_g = (const float*)d_in[6];
    const float* ln_b = (const float*)d_in[7];
    const float* thr = (const float*)d_in[8];
    float* out = (float*)d_out;

    gemm_proj4<<<dim3(8, (NB * TT) / BM), 256>>>(v_fea, a_fea,
                                                 Wv1, Wv2, Wa1, Wa2);

    beta_k<<<dim3(TT / BN, TT / BM, NB), 128>>>();
    combine_sums_k<<<(NB * TT) / 256, 256>>>();

    select_k<<<(NB * TT) / 2, 256>>>(thr);

    ln_combine_sparse<<<NB * TT, 256>>>(v_fea, a_fea, ln_g, ln_b, out);
}